// round 5
// baseline (speedup 1.0000x reference)
#include <cuda_runtime.h>
#include <cuda_bf16.h>

// Ball query: for each of NQ=32768 queries (pg), find first K=10 points of
// x (NP=8192) with d2 <= 0.0625, in ascending index order.
//
// Output (float32): [0..NQ*K) mapping (index as float), [NQ*K..NQ*K*4) coords.
//
// R5: pipelined 64-pt chunks, ballot masks deferred to SMEM + post-decode,
// dynamic work queue, float4 global mirror (x,y,z,|p|^2) for fill + tail.

#define NP 8192
#define NQ 32768
#define KNN 10
#define R2C 0.0625f
#define MAP_ELEMS (NQ * KNN)
#define NPC 2048
#define NIT (NPC / 64)       // 32
#define WPC 8                // warps per CTA
#define WBATCH 8

__device__ float4  g_xw[NP];
__device__ unsigned g_work;

__global__ void prep_kernel(const float* __restrict__ x)
{
    const int i = blockIdx.x * blockDim.x + threadIdx.x;
    if (i == 0) g_work = 0u;
    if (i < NP) {
        const float px = x[3 * i + 0];
        const float py = x[3 * i + 1];
        const float pz = x[3 * i + 2];
        const float ps = px * px + py * py + pz * pz;
        g_xw[i] = make_float4(px, py, pz, ps);
    }
}

__global__ void __launch_bounds__(256)
bq_kernel(const float* __restrict__ pg, float* __restrict__ out)
{
    __shared__ float4 pts[NPC + 64];            // +64 pad for prefetch overread
    __shared__ uint2  wmask[WPC][NIT];
    __shared__ int    idxs[WPC][16];

    for (int i = threadIdx.x; i < NPC; i += blockDim.x)
        pts[i] = g_xw[i];
    for (int i = threadIdx.x; i < 64; i += blockDim.x)
        pts[NPC + i] = make_float4(1e30f, 1e30f, 1e30f, 1e30f);
    __syncthreads();

    const int lane = threadIdx.x & 31;
    const int warp = threadIdx.x >> 5;

    for (;;) {
        unsigned q0;
        if (lane == 0) q0 = atomicAdd(&g_work, WBATCH);
        q0 = __shfl_sync(0xffffffffu, q0, 0);
        if (q0 >= NQ) break;
        const unsigned qend = (q0 + WBATCH < NQ) ? q0 + WBATCH : NQ;

        for (unsigned q = q0; q < qend; q++) {
            const float qx = pg[3 * q + 0];
            const float qy = pg[3 * q + 1];
            const float qz = pg[3 * q + 2];
            const float q2 = qx * qx + qy * qy + qz * qz;

            int cnt = 0;
            int it  = 0;

            // ---- phase 1: pipelined scan of SMEM cache, 64 pts/step ----
            float4 A = pts[lane];
            float4 B = pts[32 + lane];
            for (;;) {
                // step even: process A,B ; prefetch C,D
                float4 C = pts[it * 64 + 64 + lane];
                float4 D = pts[it * 64 + 96 + lane];
                {
                    const float dA  = qx * A.x + qy * A.y + qz * A.z;
                    const float d2A = q2 + A.w - 2.0f * dA;
                    const float dB  = qx * B.x + qy * B.y + qz * B.z;
                    const float d2B = q2 + B.w - 2.0f * dB;
                    const unsigned mA = __ballot_sync(0xffffffffu, d2A <= R2C);
                    const unsigned mB = __ballot_sync(0xffffffffu, d2B <= R2C);
                    if (lane == 0) wmask[warp][it] = make_uint2(mA, mB);
                    cnt += __popc(mA) + __popc(mB);
                }
                it++;
                if (cnt >= KNN || it == NIT) break;

                // step odd: process C,D ; prefetch A,B
                A = pts[it * 64 + 64 + lane];
                B = pts[it * 64 + 96 + lane];
                {
                    const float dC  = qx * C.x + qy * C.y + qz * C.z;
                    const float d2C = q2 + C.w - 2.0f * dC;
                    const float dD  = qx * D.x + qy * D.y + qz * D.z;
                    const float d2D = q2 + D.w - 2.0f * dD;
                    const unsigned mC = __ballot_sync(0xffffffffu, d2C <= R2C);
                    const unsigned mD = __ballot_sync(0xffffffffu, d2D <= R2C);
                    if (lane == 0) wmask[warp][it] = make_uint2(mC, mD);
                    cnt += __popc(mC) + __popc(mD);
                }
                it++;
                if (cnt >= KNN || it == NIT) break;
            }
            const int nit = it;
            __syncwarp();   // lane0's mask STS -> visible to all lanes

            // ---- decode: lane L recovers index of L-th hit ----
            const int c1 = (cnt < KNN ? cnt : KNN);
            int myidx = 0;
            if (lane < c1) {
                int cum = 0;
                for (int t = 0; t < nit; t++) {
                    const uint2 m = wmask[warp][t];
                    const int ca = __popc(m.x);
                    if (lane < cum + ca) {
                        myidx = t * 64 + (int)__fns(m.x, 0, lane - cum + 1);
                        break;
                    }
                    cum += ca;
                    const int cb = __popc(m.y);
                    if (lane < cum + cb) {
                        myidx = t * 64 + 32 + (int)__fns(m.y, 0, lane - cum + 1);
                        break;
                    }
                    cum += cb;
                }
            }

            // ---- phase 2 (rare): tail from global float4 mirror ----
            if (cnt < KNN) {
                const unsigned lt = (1u << lane) - 1u;
                for (int base = NPC; base < NP; base += 32) {
                    const float4 P = g_xw[base + lane];
                    const float d  = qx * P.x + qy * P.y + qz * P.z;
                    const float d2 = q2 + P.w - 2.0f * d;
                    const bool v = (d2 <= R2C);
                    const unsigned m = __ballot_sync(0xffffffffu, v);
                    if (v) {
                        const int slot = cnt + __popc(m & lt);
                        if (slot < KNN) idxs[warp][slot] = base + lane;
                    }
                    cnt += __popc(m);
                    if (cnt >= KNN) break;
                }
                __syncwarp();
                const int c = (cnt < KNN ? cnt : KNN);
                if (lane >= c1 && lane < c) myidx = idxs[warp][lane];
            }

            // ---- emit ----
            const int c = (cnt < KNN ? cnt : KNN);
            if (lane < KNN) {
                const bool found = (lane < c);
                float px = 0.0f, py = 0.0f, pz = 0.0f;
                if (found) {
                    const float4 P = (myidx < NPC) ? pts[myidx] : g_xw[myidx];
                    px = P.x; py = P.y; pz = P.z;
                }
                out[(size_t)q * KNN + lane] = found ? (float)myidx : 0.0f;
                float* oc = out + MAP_ELEMS + ((size_t)q * KNN + lane) * 3;
                oc[0] = px; oc[1] = py; oc[2] = pz;
            }
            __syncwarp();   // idxs/wmask reuse safety
        }
    }
}

extern "C" void kernel_launch(void* const* d_in, const int* in_sizes, int n_in,
                              void* d_out, int out_size)
{
    const float* x  = (const float*)d_in[0];   // (1, 8192, 3)
    const float* pg = (const float*)d_in[1];   // (1, 64, 32, 16, 3)
    if (n_in >= 2 && in_sizes[0] == NQ * 3 && in_sizes[1] == NP * 3) {
        const float* t = x; x = pg; pg = t;
    }
    float* out = (float*)d_out;

    static bool attr_set = false;
    if (!attr_set) {
        cudaFuncSetAttribute(bq_kernel,
                             cudaFuncAttributePreferredSharedMemoryCarveout, 100);
        attr_set = true;
    }

    prep_kernel<<<(NP + 255) / 256, 256>>>(x);
    bq_kernel<<<912, 256>>>(pg, out);   // 6 CTAs/SM persistent-ish
}

// round 6
// speedup vs baseline: 2.2163x; 2.2163x over previous
#include <cuda_runtime.h>
#include <cuda_bf16.h>

// Ball query: for each of NQ=32768 query points (p_grid), find first K=10
// points of x (NP=8192) with d2 <= RADIUS^2, ascending index order.
//
// Output buffer (float32), out_size = NQ*K + NQ*K*3:
//   [0 .. NQ*K)        mapping (index as float, 0 if not found)
//   [NQ*K .. NQ*K*4)   gathered coords (x[mapping], zeroed if not found)
//
// R6 = R3 (best: 21.4us) + three surgical deltas:
//   1. warp-uniform skip of slot code on zero-hit chunks (tail queries)
//   2. single-wave grid (888 CTAs = 6/SM), grid-stride
//   3. smem carveout hint

#define NP 8192
#define NQ 32768
#define KNN 10
#define R2C 0.0625f
#define MAP_ELEMS (NQ * KNN)
#define NPC 2048            // points cached in SMEM (32 KB as float4)
#define WARPS_PER_CTA 8

__global__ void __launch_bounds__(256)
bq_kernel(const float* __restrict__ x,
          const float* __restrict__ pg,
          float* __restrict__ out)
{
    __shared__ float4 pts[NPC];                       // 32 KB
    __shared__ int scratch[WARPS_PER_CTA][16];        // hit indices (10 used)

    for (int i = threadIdx.x; i < NPC; i += blockDim.x) {
        const float px = x[3 * i + 0];
        const float py = x[3 * i + 1];
        const float pz = x[3 * i + 2];
        const float ps = px * px + py * py + pz * pz;
        pts[i] = make_float4(px, py, pz, ps);
    }
    __syncthreads();

    const int lane   = threadIdx.x & 31;
    const int warp   = threadIdx.x >> 5;
    const int gwarp  = (blockIdx.x * blockDim.x + threadIdx.x) >> 5;
    const int nwarps = (gridDim.x * blockDim.x) >> 5;
    const unsigned lt_mask = (1u << lane) - 1u;

    for (int q = gwarp; q < NQ; q += nwarps) {
        const float qx = pg[3 * q + 0];
        const float qy = pg[3 * q + 1];
        const float qz = pg[3 * q + 2];
        const float q2 = qx * qx + qy * qy + qz * qz;

        int cnt = 0;

        // ---- phase 1: SMEM-cached prefix, 64 pts / iteration ----
        for (int base = 0; base < NPC; base += 64) {
            const float4 A = pts[base + lane];
            const float4 B = pts[base + 32 + lane];

            const float dotA = qx * A.x + qy * A.y + qz * A.z;
            const float d2A  = q2 + A.w - 2.0f * dotA;
            const float dotB = qx * B.x + qy * B.y + qz * B.z;
            const float d2B  = q2 + B.w - 2.0f * dotB;

            const bool vA = (d2A <= R2C);
            const bool vB = (d2B <= R2C);
            const unsigned mA = __ballot_sync(0xffffffffu, vA);
            const unsigned mB = __ballot_sync(0xffffffffu, vB);

            if (mA | mB) {        // warp-uniform: skip slot code on empty chunk
                if (vA) {
                    const int slot = cnt + __popc(mA & lt_mask);
                    if (slot < KNN) scratch[warp][slot] = base + lane;
                }
                const int cA = cnt + __popc(mA);
                if (vB) {
                    const int slot = cA + __popc(mB & lt_mask);
                    if (slot < KNN) scratch[warp][slot] = base + 32 + lane;
                }
                cnt = cA + __popc(mB);
                if (cnt >= KNN) break;   // warp-uniform
            }
        }

        // ---- phase 2 (rare): tail from global, identical math ----
        if (cnt < KNN) {
            for (int base = NPC; base < NP; base += 32) {
                const int i = base + lane;
                const float px = x[3 * i + 0];
                const float py = x[3 * i + 1];
                const float pz = x[3 * i + 2];
                const float ps  = px * px + py * py + pz * pz;
                const float dot = qx * px + qy * py + qz * pz;
                const float d2  = q2 + ps - 2.0f * dot;
                const bool valid = (d2 <= R2C);
                const unsigned mask = __ballot_sync(0xffffffffu, valid);
                if (valid) {
                    const int slot = cnt + __popc(mask & lt_mask);
                    if (slot < KNN) scratch[warp][slot] = i;
                }
                cnt += __popc(mask);
                if (cnt >= KNN) break;
            }
        }

        __syncwarp();   // make scratch STS visible to all lanes

        // ---- epilogue: lanes 0..9 emit mapping + coords ----
        const int c = cnt < KNN ? cnt : KNN;
        if (lane < KNN) {
            const bool found = (lane < c);
            const int idx = found ? scratch[warp][lane] : 0;
            out[(size_t)q * KNN + lane] = found ? (float)idx : 0.0f;

            float px = 0.0f, py = 0.0f, pz = 0.0f;
            if (found) {
                if (idx < NPC) {
                    const float4 t = pts[idx];
                    px = t.x; py = t.y; pz = t.z;
                } else {
                    px = x[3 * idx + 0];
                    py = x[3 * idx + 1];
                    pz = x[3 * idx + 2];
                }
            }
            float* oc = out + MAP_ELEMS + ((size_t)q * KNN + lane) * 3;
            oc[0] = px; oc[1] = py; oc[2] = pz;
        }
        __syncwarp();   // scratch reuse safety for next query
    }
}

extern "C" void kernel_launch(void* const* d_in, const int* in_sizes, int n_in,
                              void* d_out, int out_size)
{
    const float* x  = (const float*)d_in[0];   // (1, 8192, 3)
    const float* pg = (const float*)d_in[1];   // (1, 64, 32, 16, 3)
    if (n_in >= 2 && in_sizes[0] == NQ * 3 && in_sizes[1] == NP * 3) {
        const float* t = x; x = pg; pg = t;
    }
    float* out = (float*)d_out;

    static bool attr_set = false;
    if (!attr_set) {
        cudaFuncSetAttribute(bq_kernel,
                             cudaFuncAttributePreferredSharedMemoryCarveout, 100);
        attr_set = true;
    }

    const int threads = 256;
    const int blocks  = 888;    // 6 CTAs/SM x 148 SMs = single wave

    bq_kernel<<<blocks, threads>>>(x, pg, out);
}